// round 13
// baseline (speedup 1.0000x reference)
#include <cuda_runtime.h>
#include <cuda_fp16.h>
#include <cstdint>

#define B_ 4
#define N_ 2048
#define C_ 1024
#define H_ 16
#define D_ 64
#define M_ (B_*N_)   // 8192

// ---------------- scratch (device globals; allocation-free rule) ----------------
__device__ __align__(128) __half g_xh    [(size_t)M_*C_];
__device__ __align__(128) __half g_wqkvh [(size_t)3*C_*C_];
__device__ __align__(128) __half g_wprojh[(size_t)C_*C_];
__device__ __align__(128) __half g_qh[(size_t)B_*H_*N_*D_];
__device__ __align__(128) __half g_kh[(size_t)B_*H_*N_*D_];
__device__ __align__(128) __half g_vh[(size_t)B_*H_*N_*D_];
__device__ __align__(128) __half g_atth[(size_t)M_*C_];

// ---------------- PTX helpers ----------------
__device__ __forceinline__ uint32_t cvta_s(const void* p){
    return (uint32_t)__cvta_generic_to_shared(p);
}
__device__ __forceinline__ void ldsm4(uint32_t& r0, uint32_t& r1, uint32_t& r2, uint32_t& r3, uint32_t a){
    asm volatile("ldmatrix.sync.aligned.m8n8.x4.shared.b16 {%0,%1,%2,%3},[%4];"
                 : "=r"(r0),"=r"(r1),"=r"(r2),"=r"(r3) : "r"(a));
}
__device__ __forceinline__ void ldsm4t(uint32_t& r0, uint32_t& r1, uint32_t& r2, uint32_t& r3, uint32_t a){
    asm volatile("ldmatrix.sync.aligned.m8n8.x4.trans.shared.b16 {%0,%1,%2,%3},[%4];"
                 : "=r"(r0),"=r"(r1),"=r"(r2),"=r"(r3) : "r"(a));
}
__device__ __forceinline__ void mma16816(float* d, const uint32_t* a, const uint32_t* b){
    asm volatile("mma.sync.aligned.m16n8k16.row.col.f32.f16.f16.f32 "
                 "{%0,%1,%2,%3},{%4,%5,%6,%7},{%8,%9},{%0,%1,%2,%3};"
                 : "+f"(d[0]),"+f"(d[1]),"+f"(d[2]),"+f"(d[3])
                 : "r"(a[0]),"r"(a[1]),"r"(a[2]),"r"(a[3]),"r"(b[0]),"r"(b[1]));
}
__device__ __forceinline__ void cp16(uint32_t s, const void* g){
    asm volatile("cp.async.cg.shared.global [%0],[%1],16;" :: "r"(s),"l"(g));
}
__device__ __forceinline__ void cpcommit(){ asm volatile("cp.async.commit_group;"); }
template<int Ng> __device__ __forceinline__ void cpwaitg(){
    asm volatile("cp.async.wait_group %0;" :: "n"(Ng));
}
__device__ __forceinline__ void cpwait0(){ asm volatile("cp.async.wait_group 0;"); }
__device__ __forceinline__ uint32_t h2ex2(uint32_t x){
    uint32_t r; asm("ex2.approx.f16x2 %0, %1;" : "=r"(r) : "r"(x)); return r;
}

// ---------------- fused fp32 -> fp16 converter (grid-stride, 4 float4/thread) --
__global__ void __launch_bounds__(256)
f2h_all(const float* __restrict__ x, const float* __restrict__ wqkv,
        const float* __restrict__ wproj)
{
    int base = blockIdx.x*1024 + threadIdx.x;
    #pragma unroll
    for (int u=0; u<4; u++){
        int i = base + u*256;
        const float* src; __half* dst; int k;
        if (i < 2097152)      { src = x;     dst = g_xh;     k = i; }
        else if (i < 2883584) { src = wqkv;  dst = g_wqkvh;  k = i - 2097152; }
        else                  { src = wproj; dst = g_wprojh; k = i - 2883584; }
        float4 f = ((const float4*)src)[k];
        ((__half2*)dst)[k*2]   = __floats2half2_rn(f.x, f.y);
        ((__half2*)dst)[k*2+1] = __floats2half2_rn(f.z, f.w);
    }
}

// ---------------- HGEMM: 128x64 CTA tile, 4 warps, 4-stage K32 pipeline --------
// Stage layout: pairs of logical 32-col rows packed into one 128B smem row,
// chunk index (row&1)*4 + cc, swizzled by (row>>1)&7. Stage = A 8KB + B 4KB.
// 4 stages = 48KB -> same occupancy as the 2-stage kernel, but wait_group 2
// keeps two chunks in flight (pipeline slack).
// C[m,o] = sum_k A[m,k] * W[o,k]  (fp16 in, fp32 acc)
// mode 0: A=g_xh, W=g_wqkvh, scatter fp16 Q/K/V head-major
// mode 1: A=g_atth, W=g_wprojh, add bias, write fp32 out
#define TSTG32 12288               // A 8KB + B 4KB per stage
__device__ __forceinline__ uint32_t paddr(uint32_t base, int row, int cc){
    int chunk = ((row&1)<<2) + cc;                 // 0..7 within the 128B smem row
    return base + ((uint32_t)(row>>1)<<7) + ((uint32_t)(chunk ^ ((row>>1)&7))<<4);
}

__global__ void __launch_bounds__(128)
hgemm(const float* __restrict__ bias, float* __restrict__ out, int mode)
{
    __shared__ __align__(128) char smem[4*TSTG32];   // 48 KB static
    const int tid = threadIdx.x;
    const int w = tid>>5, lane = tid&31;
    const int g = lane>>2, t = lane&3;
    const int m0 = blockIdx.y*128, n0 = blockIdx.x*64;
    const int wm = (w>>1)*64, wn = (w&1)*32;

    const __half* Ap = (mode==0) ? g_xh    : g_atth;
    const __half* Wp = (mode==0) ? g_wqkvh : g_wprojh;
    const __half* Arow = Ap + (size_t)m0*C_;
    const __half* Brow = Wp + (size_t)n0*C_;

    uint32_t s0 = cvta_s(smem);

    float acc[4][4][4];
    #pragma unroll
    for (int i=0;i<4;i++)
        #pragma unroll
        for (int jj=0;jj<4;jj++)
            #pragma unroll
            for (int e=0;e<4;e++) acc[i][jj][e] = 0.f;

    // load K-chunk kt (32 cols) into stage s
    auto ldchunk = [&](int s, int kt){
        uint32_t sa = s0 + s*TSTG32;
        uint32_t sb = sa + 8192;
        const __half* a = Arow + kt*32;
        #pragma unroll
        for (int it=0; it<4; it++){
            int idx = it*128 + tid;
            int gr = idx>>2, c = idx&3;            // gr 0..127
            cp16(paddr(sa, gr, c), a + (size_t)gr*C_ + c*8);
        }
        const __half* b = Brow + kt*32;
        #pragma unroll
        for (int it=0; it<2; it++){
            int idx = it*128 + tid;
            int gr = idx>>2, c = idx&3;            // gr 0..63
            cp16(paddr(sb, gr, c), b + (size_t)gr*C_ + c*8);
        }
        cpcommit();
    };

    ldchunk(0,0); ldchunk(1,1); ldchunk(2,2);

    #pragma unroll 1
    for (int kt=0; kt<32; kt++){
        int s = kt & 3;
        if (kt < 30) cpwaitg<2>(); else if (kt == 30) cpwaitg<1>(); else cpwaitg<0>();
        __syncthreads();
        if (kt+3 < 32) ldchunk((kt+3)&3, kt+3);

        uint32_t sa = s0 + s*TSTG32;
        uint32_t sb = sa + 8192;
        #pragma unroll
        for (int ks=0; ks<2; ks++){
            uint32_t a[4][4];
            #pragma unroll
            for (int i=0;i<4;i++){
                int row = wm + 16*i + (lane&15);
                int cc  = 2*ks + (lane>>4);
                ldsm4(a[i][0],a[i][1],a[i][2],a[i][3], paddr(sa, row, cc));
            }
            uint32_t b[4][2];
            #pragma unroll
            for (int p=0;p<2;p++){
                int row = wn + 16*p + ((lane>>4)&1)*8 + (lane&7);
                int cc  = 2*ks + ((lane>>3)&1);
                uint32_t r0,r1,r2,r3; ldsm4(r0,r1,r2,r3, paddr(sb, row, cc));
                b[2*p][0]=r0; b[2*p][1]=r1; b[2*p+1][0]=r2; b[2*p+1][1]=r3;
            }
            #pragma unroll
            for (int i=0;i<4;i++)
                #pragma unroll
                for (int jj=0;jj<4;jj++)
                    mma16816(acc[i][jj], a[i], b[jj]);
        }
    }

    if (mode == 0){
        int which = n0 >> 10;
        int h     = (n0 >> 6) & 15;
        int b2    = m0 >> 11;
        __half* dst = ((which==0) ? g_qh : (which==1) ? g_kh : g_vh)
                    + ((size_t)(b2*H_ + h))*N_*D_;
        #pragma unroll
        for (int i=0;i<4;i++){
            int rlo = (m0 & 2047) + wm + 16*i + g;
            #pragma unroll
            for (int jj=0;jj<4;jj++){
                int d = wn + 8*jj + 2*t;
                __half2 lo = __floats2half2_rn(acc[i][jj][0], acc[i][jj][1]);
                __half2 hi = __floats2half2_rn(acc[i][jj][2], acc[i][jj][3]);
                *(__half2*)(dst + (size_t)rlo*D_ + d)     = lo;
                *(__half2*)(dst + (size_t)(rlo+8)*D_ + d) = hi;
            }
        }
    } else {
        #pragma unroll
        for (int i=0;i<4;i++){
            int gm = m0 + wm + 16*i + g;
            #pragma unroll
            for (int jj=0;jj<4;jj++){
                int gn = n0 + wn + 8*jj + 2*t;
                float bx = bias[gn], by = bias[gn+1];
                float2 lo = make_float2(acc[i][jj][0]+bx, acc[i][jj][1]+by);
                float2 hi = make_float2(acc[i][jj][2]+bx, acc[i][jj][3]+by);
                *(float2*)(out + (size_t)gm*C_ + gn)     = lo;
                *(float2*)(out + (size_t)(gm+8)*C_ + gn) = hi;
            }
        }
    }
}

// ---------------- flash attention (R11 proven best config) ---------------------
// 4 warps, 64 queries, LPT order, prescaled Q, packed h2 max, MMA l-sum.
__global__ void __launch_bounds__(128)
flash16()
{
    __shared__ __align__(16) __half Qs[64*64];
    __shared__ __align__(16) __half Ks[2][64*64];
    __shared__ __align__(16) __half Vs[2][64*64];

    const int tid = threadIdx.x, w = tid>>5, lane = tid&31;
    const int g = lane>>2, t = lane&3;
    const int qb = (int)(gridDim.x - 1u - blockIdx.x);
    const int bh = blockIdx.y;
    const int qbase = qb*64;
    const size_t hoff = (size_t)bh*N_*D_;
    const __half* Qg = g_qh + hoff;
    const __half* Kg = g_kh + hoff;
    const __half* Vg = g_vh + hoff;

    uint32_t qs_b = cvta_s(Qs);
    uint32_t ks_b[2] = { cvta_s(Ks[0]), cvta_s(Ks[1]) };
    uint32_t vs_b[2] = { cvta_s(Vs[0]), cvta_s(Vs[1]) };

    auto ldkv = [&](int buf, int j){
        const __half* ks = Kg + (size_t)j*64*D_;
        const __half* vs = Vg + (size_t)j*64*D_;
        #pragma unroll
        for (int it=0; it<4; it++){
            int idx = it*128 + tid, r = idx>>3, c = idx&7;
            uint32_t off = (r<<7) + (((c^(r&7)))<<4);
            cp16(ks_b[buf] + off, ks + (size_t)r*D_ + c*8);
            cp16(vs_b[buf] + off, vs + (size_t)r*D_ + c*8);
        }
    };

    ldkv(0, 0); cpcommit();

    #pragma unroll
    for (int it=0; it<4; it++){
        int idx = it*128 + tid, r = idx>>3, c = idx&7;
        float4 v = *(const float4*)(Qg + (size_t)(qbase+r)*D_ + c*8);
        *(float4*)((char*)Qs + (r<<7) + (((c^(r&7)))<<4)) = v;
    }
    __syncthreads();

    const __half2 sc2 = __float2half2_rn(0.18033688011112042f);
    uint32_t qf[4][4];
    #pragma unroll
    for (int ks=0; ks<4; ks++){
        int row = 16*w + (lane&15);
        uint32_t addr = qs_b + (row<<7) + ((((2*ks + (lane>>4)) ^ (row&7)))<<4);
        ldsm4(qf[ks][0],qf[ks][1],qf[ks][2],qf[ks][3], addr);
        #pragma unroll
        for (int e=0;e<4;e++){
            __half2 q = *(__half2*)&qf[ks][e];
            q = __hmul2(q, sc2);
            qf[ks][e] = *(uint32_t*)&q;
        }
    }

    __half2 m2 = __float2half2_rn(-60000.f);
    float lacc[4] = {0.f, 0.f, 0.f, 0.f};
    const uint32_t ONES2 = 0x3C003C00u;
    const uint32_t bones[2] = { ONES2, ONES2 };
    float o[8][4];
    #pragma unroll
    for (int jj=0;jj<8;jj++)
        #pragma unroll
        for (int e=0;e<4;e++) o[jj][e]=0.f;

    const int qlo = qbase + 16*w + g;
    const int qhi = qlo + 8;

    for (int j=0; j<=qb; j++){
        int buf = j&1;
        cpwait0(); __syncthreads();
        if (j < qb){ ldkv(buf^1, j+1); cpcommit(); }

        float s[8][4];
        #pragma unroll
        for (int jj=0;jj<8;jj++)
            #pragma unroll
            for (int e=0;e<4;e++) s[jj][e]=0.f;

        #pragma unroll
        for (int ks=0; ks<4; ks++){
            uint32_t kf[8][2];
            #pragma unroll
            for (int p=0;p<4;p++){
                int row = 16*p + ((lane>>4)&1)*8 + (lane&7);
                uint32_t addr = ks_b[buf] + (row<<7) + ((((2*ks + ((lane>>3)&1)) ^ (row&7)))<<4);
                uint32_t r0,r1,r2,r3; ldsm4(r0,r1,r2,r3, addr);
                kf[2*p][0]=r0; kf[2*p][1]=r1; kf[2*p+1][0]=r2; kf[2*p+1][1]=r3;
            }
            #pragma unroll
            for (int jj=0;jj<8;jj++) mma16816(s[jj], qf[ks], kf[jj]);
        }

        const bool diag = (j == qb);
        uint32_t zf[8][2];
        __half2 pmax_lo = __float2half2_rn(-60000.f);
        __half2 pmax_hi = __float2half2_rn(-60000.f);
        #pragma unroll
        for (int jj=0;jj<8;jj++){
            float z0 = s[jj][0], z1 = s[jj][1], z2 = s[jj][2], z3 = s[jj][3];
            if (diag){
                int c0 = j*64 + 8*jj + 2*t;
                if (c0   > qlo) z0 = -60000.f;
                if (c0+1 > qlo) z1 = -60000.f;
                if (c0   > qhi) z2 = -60000.f;
                if (c0+1 > qhi) z3 = -60000.f;
            }
            __half2 zlo = __floats2half2_rn(z0, z1);
            __half2 zhi = __floats2half2_rn(z2, z3);
            zf[jj][0] = *(uint32_t*)&zlo;
            zf[jj][1] = *(uint32_t*)&zhi;
            pmax_lo = __hmax2(pmax_lo, zlo);
            pmax_hi = __hmax2(pmax_hi, zhi);
        }
        pmax_lo = __hmax2(pmax_lo, __lowhigh2highlow(pmax_lo));
        pmax_hi = __hmax2(pmax_hi, __lowhigh2highlow(pmax_hi));
        __half2 mt2 = __halves2half2(__low2half(pmax_lo), __low2half(pmax_hi));
        {
            uint32_t mb = *(uint32_t*)&mt2;
            uint32_t s1 = __shfl_xor_sync(0xffffffffu, mb, 1);
            mt2 = __hmax2(mt2, *(__half2*)&s1);
            mb = *(uint32_t*)&mt2;
            uint32_t s2 = __shfl_xor_sync(0xffffffffu, mb, 2);
            mt2 = __hmax2(mt2, *(__half2*)&s2);
        }
        __half2 m2new = __hmax2(m2, mt2);

        float alpha_lo = exp2f(__low2float(m2)  - __low2float(m2new));
        float alpha_hi = exp2f(__high2float(m2) - __high2float(m2new));
        m2 = m2new;

        __half2 mlo2 = __half2half2(__low2half(m2));
        __half2 mhi2 = __half2half2(__high2half(m2));

        uint32_t pf[8][2];
        #pragma unroll
        for (int jj=0;jj<8;jj++){
            __half2 dlo = __hsub2(*(__half2*)&zf[jj][0], mlo2);
            __half2 dhi = __hsub2(*(__half2*)&zf[jj][1], mhi2);
            pf[jj][0] = h2ex2(*(uint32_t*)&dlo);
            pf[jj][1] = h2ex2(*(uint32_t*)&dhi);
        }

        lacc[0] *= alpha_lo; lacc[1] *= alpha_lo;
        lacc[2] *= alpha_hi; lacc[3] *= alpha_hi;
        #pragma unroll
        for (int jj=0;jj<8;jj++){
            o[jj][0]*=alpha_lo; o[jj][1]*=alpha_lo;
            o[jj][2]*=alpha_hi; o[jj][3]*=alpha_hi;
        }

        #pragma unroll
        for (int ks=0; ks<4; ks++){
            uint32_t vf[8][2];
            #pragma unroll
            for (int p=0;p<4;p++){
                int row = 16*ks + ((lane>>3)&1)*8 + (lane&7);
                uint32_t addr = vs_b[buf] + (row<<7) + ((((2*p + (lane>>4)) ^ (row&7)))<<4);
                uint32_t r0,r1,r2,r3; ldsm4t(r0,r1,r2,r3, addr);
                vf[2*p][0]=r0; vf[2*p][1]=r1; vf[2*p+1][0]=r2; vf[2*p+1][1]=r3;
            }
            uint32_t af[4] = { pf[2*ks][0], pf[2*ks][1], pf[2*ks+1][0], pf[2*ks+1][1] };
            #pragma unroll
            for (int jj=0;jj<8;jj++) mma16816(o[jj], af, vf[jj]);
            mma16816(lacc, af, bones);
        }
    }

    float inv_lo = 1.f/lacc[0], inv_hi = 1.f/lacc[2];
    int h = bh & 15, b2 = bh >> 4;
    __half* outp  = g_atth + ((size_t)(b2*N_ + qlo))*C_ + h*D_;
    __half* outp2 = outp + (size_t)8*C_;
    #pragma unroll
    for (int jj=0;jj<8;jj++){
        __half2 lo = __floats2half2_rn(o[jj][0]*inv_lo, o[jj][1]*inv_lo);
        __half2 hi = __floats2half2_rn(o[jj][2]*inv_hi, o[jj][3]*inv_hi);
        *(__half2*)(outp  + 8*jj + 2*t) = lo;
        *(__half2*)(outp2 + 8*jj + 2*t) = hi;
    }
}

// ---------------- launch ----------------
extern "C" void kernel_launch(void* const* d_in, const int* in_sizes, int n_in,
                              void* d_out, int out_size)
{
    const float* x      = (const float*)d_in[0];
    const float* qkv_w  = (const float*)d_in[1];
    const float* proj_w = (const float*)d_in[2];
    const float* proj_b = (const float*)d_in[3];
    float* out = (float*)d_out;

    f2h_all<<<3072, 256>>>(x, qkv_w, proj_w);

    // QKV: 48 n-tiles, 64 m-tiles
    hgemm<<<dim3(48, 64), 128>>>(nullptr, nullptr, 0);
    // attention: R11 proven 64-query config
    flash16<<<dim3(N_/64, B_*H_), 128>>>();
    // out proj
    hgemm<<<dim3(16, 64), 128>>>(proj_b, out, 1);
}

// round 14
// speedup vs baseline: 1.0949x; 1.0949x over previous
#include <cuda_runtime.h>
#include <cuda_fp16.h>
#include <cstdint>

#define B_ 4
#define N_ 2048
#define C_ 1024
#define H_ 16
#define D_ 64
#define M_ (B_*N_)   // 8192

// ---------------- scratch (device globals; allocation-free rule) ----------------
__device__ __align__(128) __half g_xh    [(size_t)M_*C_];
__device__ __align__(128) __half g_wqkvh [(size_t)3*C_*C_];
__device__ __align__(128) __half g_wprojh[(size_t)C_*C_];
__device__ __align__(128) __half g_qh[(size_t)B_*H_*N_*D_];
__device__ __align__(128) __half g_kh[(size_t)B_*H_*N_*D_];
__device__ __align__(128) __half g_vh[(size_t)B_*H_*N_*D_];
__device__ __align__(128) __half g_atth[(size_t)M_*C_];

// ---------------- PTX helpers ----------------
__device__ __forceinline__ uint32_t cvta_s(const void* p){
    return (uint32_t)__cvta_generic_to_shared(p);
}
__device__ __forceinline__ void ldsm4(uint32_t& r0, uint32_t& r1, uint32_t& r2, uint32_t& r3, uint32_t a){
    asm volatile("ldmatrix.sync.aligned.m8n8.x4.shared.b16 {%0,%1,%2,%3},[%4];"
                 : "=r"(r0),"=r"(r1),"=r"(r2),"=r"(r3) : "r"(a));
}
__device__ __forceinline__ void ldsm4t(uint32_t& r0, uint32_t& r1, uint32_t& r2, uint32_t& r3, uint32_t a){
    asm volatile("ldmatrix.sync.aligned.m8n8.x4.trans.shared.b16 {%0,%1,%2,%3},[%4];"
                 : "=r"(r0),"=r"(r1),"=r"(r2),"=r"(r3) : "r"(a));
}
__device__ __forceinline__ void mma16816(float* d, const uint32_t* a, const uint32_t* b){
    asm volatile("mma.sync.aligned.m16n8k16.row.col.f32.f16.f16.f32 "
                 "{%0,%1,%2,%3},{%4,%5,%6,%7},{%8,%9},{%0,%1,%2,%3};"
                 : "+f"(d[0]),"+f"(d[1]),"+f"(d[2]),"+f"(d[3])
                 : "r"(a[0]),"r"(a[1]),"r"(a[2]),"r"(a[3]),"r"(b[0]),"r"(b[1]));
}
__device__ __forceinline__ void cp16(uint32_t s, const void* g){
    asm volatile("cp.async.cg.shared.global [%0],[%1],16;" :: "r"(s),"l"(g));
}
__device__ __forceinline__ void cpcommit(){ asm volatile("cp.async.commit_group;"); }
template<int Ng> __device__ __forceinline__ void cpwaitg(){
    asm volatile("cp.async.wait_group %0;" :: "n"(Ng));
}
__device__ __forceinline__ void cpwait0(){ asm volatile("cp.async.wait_group 0;"); }
__device__ __forceinline__ uint32_t h2ex2(uint32_t x){
    uint32_t r; asm("ex2.approx.f16x2 %0, %1;" : "=r"(r) : "r"(x)); return r;
}

// ---------------- fused fp32 -> fp16 converter (grid-stride, 4 float4/thread) --
__global__ void __launch_bounds__(256)
f2h_all(const float* __restrict__ x, const float* __restrict__ wqkv,
        const float* __restrict__ wproj)
{
    int base = blockIdx.x*1024 + threadIdx.x;
    #pragma unroll
    for (int u=0; u<4; u++){
        int i = base + u*256;
        const float* src; __half* dst; int k;
        if (i < 2097152)      { src = x;     dst = g_xh;     k = i; }
        else if (i < 2883584) { src = wqkv;  dst = g_wqkvh;  k = i - 2097152; }
        else                  { src = wproj; dst = g_wprojh; k = i - 2883584; }
        float4 f = ((const float4*)src)[k];
        ((__half2*)dst)[k*2]   = __floats2half2_rn(f.x, f.y);
        ((__half2*)dst)[k*2+1] = __floats2half2_rn(f.z, f.w);
    }
}

// ---------------- HGEMM 2-stage (R8 proven; used for QKV) ----------------------
// C[m,o] = sum_k A[m,k] * W[o,k]  (fp16 in, fp32 acc); scatter Q/K/V head-major
__global__ void __launch_bounds__(128)
hgemm(const float* __restrict__ bias, float* __restrict__ out, int mode)
{
    __shared__ __align__(16) __half As[2][128*64];
    __shared__ __align__(16) __half Bs[2][64*64];
    const int tid = threadIdx.x;
    const int w = tid>>5, lane = tid&31;
    const int g = lane>>2, t = lane&3;
    const int m0 = blockIdx.y*128, n0 = blockIdx.x*64;
    const int wm = (w>>1)*64, wn = (w&1)*32;

    const __half* Ap = (mode==0) ? g_xh    : g_atth;
    const __half* Wp = (mode==0) ? g_wqkvh : g_wprojh;

    uint32_t as_b[2] = { cvta_s(As[0]), cvta_s(As[1]) };
    uint32_t bs_b[2] = { cvta_s(Bs[0]), cvta_s(Bs[1]) };

    float acc[4][4][4];
    #pragma unroll
    for (int i=0;i<4;i++)
        #pragma unroll
        for (int jj=0;jj<4;jj++)
            #pragma unroll
            for (int e=0;e<4;e++) acc[i][jj][e] = 0.f;

    auto ldtile = [&](int buf, int kt){
        const __half* a = Ap + (size_t)m0*C_ + kt*64;
        #pragma unroll
        for (int it=0; it<8; it++){
            int idx = it*128 + tid, r = idx>>3, c = idx&7;
            cp16(as_b[buf] + (r<<7) + (((c^(r&7)))<<4), a + (size_t)r*C_ + c*8);
        }
        const __half* bsrc = Wp + (size_t)n0*C_ + kt*64;
        #pragma unroll
        for (int it=0; it<4; it++){
            int idx = it*128 + tid, r = idx>>3, c = idx&7;
            cp16(bs_b[buf] + (r<<7) + (((c^(r&7)))<<4), bsrc + (size_t)r*C_ + c*8);
        }
    };

    ldtile(0, 0); cpcommit();

    for (int kt=0; kt<16; kt++){
        int buf = kt&1;
        cpwait0(); __syncthreads();
        if (kt < 15){ ldtile(buf^1, kt+1); cpcommit(); }

        #pragma unroll
        for (int ks=0; ks<4; ks++){
            uint32_t a[4][4];
            #pragma unroll
            for (int i=0;i<4;i++){
                int row = wm + 16*i + (lane&15);
                uint32_t addr = as_b[buf] + (row<<7) + ((((2*ks + (lane>>4)) ^ (row&7)))<<4);
                ldsm4(a[i][0],a[i][1],a[i][2],a[i][3], addr);
            }
            uint32_t b[4][2];
            #pragma unroll
            for (int p=0;p<2;p++){
                int row = wn + 16*p + ((lane>>4)&1)*8 + (lane&7);
                uint32_t addr = bs_b[buf] + (row<<7) + ((((2*ks + ((lane>>3)&1)) ^ (row&7)))<<4);
                uint32_t r0,r1,r2,r3; ldsm4(r0,r1,r2,r3, addr);
                b[2*p][0]=r0; b[2*p][1]=r1; b[2*p+1][0]=r2; b[2*p+1][1]=r3;
            }
            #pragma unroll
            for (int i=0;i<4;i++)
                #pragma unroll
                for (int jj=0;jj<4;jj++)
                    mma16816(acc[i][jj], a[i], b[jj]);
        }
    }

    if (mode == 0){
        int which = n0 >> 10;
        int h     = (n0 >> 6) & 15;
        int b2    = m0 >> 11;
        __half* dst = ((which==0) ? g_qh : (which==1) ? g_kh : g_vh)
                    + ((size_t)(b2*H_ + h))*N_*D_;
        #pragma unroll
        for (int i=0;i<4;i++){
            int rlo = (m0 & 2047) + wm + 16*i + g;
            #pragma unroll
            for (int jj=0;jj<4;jj++){
                int d = wn + 8*jj + 2*t;
                __half2 lo = __floats2half2_rn(acc[i][jj][0], acc[i][jj][1]);
                __half2 hi = __floats2half2_rn(acc[i][jj][2], acc[i][jj][3]);
                *(__half2*)(dst + (size_t)rlo*D_ + d)     = lo;
                *(__half2*)(dst + (size_t)(rlo+8)*D_ + d) = hi;
            }
        }
    } else {
        #pragma unroll
        for (int i=0;i<4;i++){
            int gm = m0 + wm + 16*i + g;
            #pragma unroll
            for (int jj=0;jj<4;jj++){
                int gn = n0 + wn + 8*jj + 2*t;
                float bx = bias[gn], by = bias[gn+1];
                float2 lo = make_float2(acc[i][jj][0]+bx, acc[i][jj][1]+by);
                float2 hi = make_float2(acc[i][jj][2]+bx, acc[i][jj][3]+by);
                *(float2*)(out + (size_t)gm*C_ + gn)     = lo;
                *(float2*)(out + (size_t)(gm+8)*C_ + gn) = hi;
            }
        }
    }
}

// ---------------- HGEMM 3-stage (R9 variant; measured best for proj) -----------
#define TSTG3 24576                // A 16KB + B 8KB per stage
#define GEMM3_SMEM (3*TSTG3)       // 72 KB

__global__ void __launch_bounds__(128)
hgemm3(const float* __restrict__ bias, float* __restrict__ out)
{
    extern __shared__ __align__(128) char smem[];
    const int tid = threadIdx.x;
    const int w = tid>>5, lane = tid&31;
    const int g = lane>>2, t = lane&3;
    const int m0 = blockIdx.y*128, n0 = blockIdx.x*64;
    const int wm = (w>>1)*64, wn = (w&1)*32;

    const __half* Arow = g_atth  + (size_t)m0*C_;
    const __half* Brow = g_wprojh + (size_t)n0*C_;

    uint32_t s0 = cvta_s(smem);

    float acc[4][4][4];
    #pragma unroll
    for (int i=0;i<4;i++)
        #pragma unroll
        for (int jj=0;jj<4;jj++)
            #pragma unroll
            for (int e=0;e<4;e++) acc[i][jj][e] = 0.f;

    auto ldchunk = [&](int s, int kt){
        uint32_t sa = s0 + s*TSTG3;
        uint32_t sb = sa + 16384;
        const __half* a = Arow + kt*64;
        #pragma unroll
        for (int it=0; it<8; it++){
            int idx = it*128 + tid, r = idx>>3, c = idx&7;
            cp16(sa + (r<<7) + ((c^(r&7))<<4), a + (size_t)r*C_ + c*8);
        }
        const __half* b = Brow + kt*64;
        #pragma unroll
        for (int it=0; it<4; it++){
            int idx = it*128 + tid, r = idx>>3, c = idx&7;
            cp16(sb + (r<<7) + ((c^(r&7))<<4), b + (size_t)r*C_ + c*8);
        }
        cpcommit();
    };

    ldchunk(0,0); ldchunk(1,1);

    #pragma unroll 1
    for (int kt=0; kt<16; kt++){
        int s = kt % 3;
        if (kt < 15) cpwaitg<1>(); else cpwaitg<0>();
        __syncthreads();
        if (kt+2 < 16) ldchunk((kt+2)%3, kt+2);

        uint32_t sa = s0 + s*TSTG3;
        uint32_t sb = sa + 16384;
        #pragma unroll
        for (int ks=0; ks<4; ks++){
            uint32_t a[4][4];
            #pragma unroll
            for (int i=0;i<4;i++){
                int row = wm + 16*i + (lane&15);
                uint32_t addr = sa + (row<<7) + ((((2*ks + (lane>>4)) ^ (row&7)))<<4);
                ldsm4(a[i][0],a[i][1],a[i][2],a[i][3], addr);
            }
            uint32_t b[4][2];
            #pragma unroll
            for (int p=0;p<2;p++){
                int row = wn + 16*p + ((lane>>4)&1)*8 + (lane&7);
                uint32_t addr = sb + (row<<7) + ((((2*ks + ((lane>>3)&1)) ^ (row&7)))<<4);
                uint32_t r0,r1,r2,r3; ldsm4(r0,r1,r2,r3, addr);
                b[2*p][0]=r0; b[2*p][1]=r1; b[2*p+1][0]=r2; b[2*p+1][1]=r3;
            }
            #pragma unroll
            for (int i=0;i<4;i++)
                #pragma unroll
                for (int jj=0;jj<4;jj++)
                    mma16816(acc[i][jj], a[i], b[jj]);
        }
    }

    #pragma unroll
    for (int i=0;i<4;i++){
        int gm = m0 + wm + 16*i + g;
        #pragma unroll
        for (int jj=0;jj<4;jj++){
            int gn = n0 + wn + 8*jj + 2*t;
            float bx = bias[gn], by = bias[gn+1];
            float2 lo = make_float2(acc[i][jj][0]+bx, acc[i][jj][1]+by);
            float2 hi = make_float2(acc[i][jj][2]+bx, acc[i][jj][3]+by);
            *(float2*)(out + (size_t)gm*C_ + gn)     = lo;
            *(float2*)(out + (size_t)(gm+8)*C_ + gn) = hi;
        }
    }
}

// ---------------- flash attention (R11 proven best config) ---------------------
// 4 warps, 64 queries, LPT order, prescaled Q, packed h2 max, MMA l-sum.
__global__ void __launch_bounds__(128)
flash16()
{
    __shared__ __align__(16) __half Qs[64*64];
    __shared__ __align__(16) __half Ks[2][64*64];
    __shared__ __align__(16) __half Vs[2][64*64];

    const int tid = threadIdx.x, w = tid>>5, lane = tid&31;
    const int g = lane>>2, t = lane&3;
    const int qb = (int)(gridDim.x - 1u - blockIdx.x);
    const int bh = blockIdx.y;
    const int qbase = qb*64;
    const size_t hoff = (size_t)bh*N_*D_;
    const __half* Qg = g_qh + hoff;
    const __half* Kg = g_kh + hoff;
    const __half* Vg = g_vh + hoff;

    uint32_t qs_b = cvta_s(Qs);
    uint32_t ks_b[2] = { cvta_s(Ks[0]), cvta_s(Ks[1]) };
    uint32_t vs_b[2] = { cvta_s(Vs[0]), cvta_s(Vs[1]) };

    auto ldkv = [&](int buf, int j){
        const __half* ks = Kg + (size_t)j*64*D_;
        const __half* vs = Vg + (size_t)j*64*D_;
        #pragma unroll
        for (int it=0; it<4; it++){
            int idx = it*128 + tid, r = idx>>3, c = idx&7;
            uint32_t off = (r<<7) + (((c^(r&7)))<<4);
            cp16(ks_b[buf] + off, ks + (size_t)r*D_ + c*8);
            cp16(vs_b[buf] + off, vs + (size_t)r*D_ + c*8);
        }
    };

    ldkv(0, 0); cpcommit();

    #pragma unroll
    for (int it=0; it<4; it++){
        int idx = it*128 + tid, r = idx>>3, c = idx&7;
        float4 v = *(const float4*)(Qg + (size_t)(qbase+r)*D_ + c*8);
        *(float4*)((char*)Qs + (r<<7) + (((c^(r&7)))<<4)) = v;
    }
    __syncthreads();

    const __half2 sc2 = __float2half2_rn(0.18033688011112042f);
    uint32_t qf[4][4];
    #pragma unroll
    for (int ks=0; ks<4; ks++){
        int row = 16*w + (lane&15);
        uint32_t addr = qs_b + (row<<7) + ((((2*ks + (lane>>4)) ^ (row&7)))<<4);
        ldsm4(qf[ks][0],qf[ks][1],qf[ks][2],qf[ks][3], addr);
        #pragma unroll
        for (int e=0;e<4;e++){
            __half2 q = *(__half2*)&qf[ks][e];
            q = __hmul2(q, sc2);
            qf[ks][e] = *(uint32_t*)&q;
        }
    }

    __half2 m2 = __float2half2_rn(-60000.f);
    float lacc[4] = {0.f, 0.f, 0.f, 0.f};
    const uint32_t ONES2 = 0x3C003C00u;
    const uint32_t bones[2] = { ONES2, ONES2 };
    float o[8][4];
    #pragma unroll
    for (int jj=0;jj<8;jj++)
        #pragma unroll
        for (int e=0;e<4;e++) o[jj][e]=0.f;

    const int qlo = qbase + 16*w + g;
    const int qhi = qlo + 8;

    for (int j=0; j<=qb; j++){
        int buf = j&1;
        cpwait0(); __syncthreads();
        if (j < qb){ ldkv(buf^1, j+1); cpcommit(); }

        float s[8][4];
        #pragma unroll
        for (int jj=0;jj<8;jj++)
            #pragma unroll
            for (int e=0;e<4;e++) s[jj][e]=0.f;

        #pragma unroll
        for (int ks=0; ks<4; ks++){
            uint32_t kf[8][2];
            #pragma unroll
            for (int p=0;p<4;p++){
                int row = 16*p + ((lane>>4)&1)*8 + (lane&7);
                uint32_t addr = ks_b[buf] + (row<<7) + ((((2*ks + ((lane>>3)&1)) ^ (row&7)))<<4);
                uint32_t r0,r1,r2,r3; ldsm4(r0,r1,r2,r3, addr);
                kf[2*p][0]=r0; kf[2*p][1]=r1; kf[2*p+1][0]=r2; kf[2*p+1][1]=r3;
            }
            #pragma unroll
            for (int jj=0;jj<8;jj++) mma16816(s[jj], qf[ks], kf[jj]);
        }

        const bool diag = (j == qb);
        uint32_t zf[8][2];
        __half2 pmax_lo = __float2half2_rn(-60000.f);
        __half2 pmax_hi = __float2half2_rn(-60000.f);
        #pragma unroll
        for (int jj=0;jj<8;jj++){
            float z0 = s[jj][0], z1 = s[jj][1], z2 = s[jj][2], z3 = s[jj][3];
            if (diag){
                int c0 = j*64 + 8*jj + 2*t;
                if (c0   > qlo) z0 = -60000.f;
                if (c0+1 > qlo) z1 = -60000.f;
                if (c0   > qhi) z2 = -60000.f;
                if (c0+1 > qhi) z3 = -60000.f;
            }
            __half2 zlo = __floats2half2_rn(z0, z1);
            __half2 zhi = __floats2half2_rn(z2, z3);
            zf[jj][0] = *(uint32_t*)&zlo;
            zf[jj][1] = *(uint32_t*)&zhi;
            pmax_lo = __hmax2(pmax_lo, zlo);
            pmax_hi = __hmax2(pmax_hi, zhi);
        }
        pmax_lo = __hmax2(pmax_lo, __lowhigh2highlow(pmax_lo));
        pmax_hi = __hmax2(pmax_hi, __lowhigh2highlow(pmax_hi));
        __half2 mt2 = __halves2half2(__low2half(pmax_lo), __low2half(pmax_hi));
        {
            uint32_t mb = *(uint32_t*)&mt2;
            uint32_t s1 = __shfl_xor_sync(0xffffffffu, mb, 1);
            mt2 = __hmax2(mt2, *(__half2*)&s1);
            mb = *(uint32_t*)&mt2;
            uint32_t s2 = __shfl_xor_sync(0xffffffffu, mb, 2);
            mt2 = __hmax2(mt2, *(__half2*)&s2);
        }
        __half2 m2new = __hmax2(m2, mt2);

        float alpha_lo = exp2f(__low2float(m2)  - __low2float(m2new));
        float alpha_hi = exp2f(__high2float(m2) - __high2float(m2new));
        m2 = m2new;

        __half2 mlo2 = __half2half2(__low2half(m2));
        __half2 mhi2 = __half2half2(__high2half(m2));

        uint32_t pf[8][2];
        #pragma unroll
        for (int jj=0;jj<8;jj++){
            __half2 dlo = __hsub2(*(__half2*)&zf[jj][0], mlo2);
            __half2 dhi = __hsub2(*(__half2*)&zf[jj][1], mhi2);
            pf[jj][0] = h2ex2(*(uint32_t*)&dlo);
            pf[jj][1] = h2ex2(*(uint32_t*)&dhi);
        }

        lacc[0] *= alpha_lo; lacc[1] *= alpha_lo;
        lacc[2] *= alpha_hi; lacc[3] *= alpha_hi;
        #pragma unroll
        for (int jj=0;jj<8;jj++){
            o[jj][0]*=alpha_lo; o[jj][1]*=alpha_lo;
            o[jj][2]*=alpha_hi; o[jj][3]*=alpha_hi;
        }

        #pragma unroll
        for (int ks=0; ks<4; ks++){
            uint32_t vf[8][2];
            #pragma unroll
            for (int p=0;p<4;p++){
                int row = 16*ks + ((lane>>3)&1)*8 + (lane&7);
                uint32_t addr = vs_b[buf] + (row<<7) + ((((2*p + (lane>>4)) ^ (row&7)))<<4);
                uint32_t r0,r1,r2,r3; ldsm4t(r0,r1,r2,r3, addr);
                vf[2*p][0]=r0; vf[2*p][1]=r1; vf[2*p+1][0]=r2; vf[2*p+1][1]=r3;
            }
            uint32_t af[4] = { pf[2*ks][0], pf[2*ks][1], pf[2*ks+1][0], pf[2*ks+1][1] };
            #pragma unroll
            for (int jj=0;jj<8;jj++) mma16816(o[jj], af, vf[jj]);
            mma16816(lacc, af, bones);
        }
    }

    float inv_lo = 1.f/lacc[0], inv_hi = 1.f/lacc[2];
    int h = bh & 15, b2 = bh >> 4;
    __half* outp  = g_atth + ((size_t)(b2*N_ + qlo))*C_ + h*D_;
    __half* outp2 = outp + (size_t)8*C_;
    #pragma unroll
    for (int jj=0;jj<8;jj++){
        __half2 lo = __floats2half2_rn(o[jj][0]*inv_lo, o[jj][1]*inv_lo);
        __half2 hi = __floats2half2_rn(o[jj][2]*inv_hi, o[jj][3]*inv_hi);
        *(__half2*)(outp  + 8*jj + 2*t) = lo;
        *(__half2*)(outp2 + 8*jj + 2*t) = hi;
    }
}

// ---------------- launch ----------------
extern "C" void kernel_launch(void* const* d_in, const int* in_sizes, int n_in,
                              void* d_out, int out_size)
{
    const float* x      = (const float*)d_in[0];
    const float* qkv_w  = (const float*)d_in[1];
    const float* proj_w = (const float*)d_in[2];
    const float* proj_b = (const float*)d_in[3];
    float* out = (float*)d_out;

    cudaFuncSetAttribute(hgemm3, cudaFuncAttributeMaxDynamicSharedMemorySize, GEMM3_SMEM);

    f2h_all<<<3072, 256>>>(x, qkv_w, proj_w);

    // QKV: 2-stage variant (its measured best)
    hgemm<<<dim3(48, 64), 128>>>(nullptr, nullptr, 0);
    // attention: R11 proven config
    flash16<<<dim3(N_/64, B_*H_), 128>>>();
    // out proj: 3-stage variant (its measured best)
    hgemm3<<<dim3(16, 64), 128, GEMM3_SMEM>>>(proj_b, out);
}